// round 17
// baseline (speedup 1.0000x reference)
#include <cuda_runtime.h>
#include <cuda_bf16.h>
#include <cstdint>
#include <cstddef>

// ----------------------------------------------------------------------------
// SCNN via warp-level HMMA (mma.sync bf16, fp32 accum), persistent CTAs.
// R16: double-buffered Y + ONE barrier per tile -> sconv(t+1) and GEMM(t)
// overlap across warps (fma pipe + tensor pipe busy simultaneously).
// M=128, 8 warps x m16, pc-fused GEMM1->GEMM2, Wexp gmem, 2 CTAs/SM.
// Keeps R15 instruction cuts: fp32x2 sconv, cvt.rn.bf16x2 splits.
// ----------------------------------------------------------------------------

#define NB_TOTAL 50000
#define NC 45
#define ND 90
#define NTT 256
#define MTILE 128
#define MSTR 136     // Y [k][m] row length (128 + 8 pad); 272B rows
#define B1STR  56    // B1 [n=96][k=48], 112B rows
#define B2STR 104    // B2 [n=48][k=96], 208B rows

__device__ float g_bufA[(size_t)NB_TOTAL * 64 * NC];
__device__ float g_bufB[(size_t)NB_TOTAL * 32 * NC];
__device__ __nv_bfloat16 g_B1h[96 * 48], g_B1l[96 * 48];
__device__ __nv_bfloat16 g_B2h[48 * 96], g_B2l[48 * 96];
// Expanded weights, layout [g][c][o] per layer (o contiguous)
__device__ float g_Wexp[26240];
// layer offsets: L1 0, L2 320, L3 2880, L4 13120, L5 23360, L6 25920

// ---------------- smem layout (bytes) ---------------------------------------
#define OFF_B1H 0
#define OFF_B1L 10752
#define OFF_B2H 21504
#define OFF_B2L 31488
#define OFF_Y   41472          /* 2 buffers x (Yh 13056 + Yl 13056) */
#define YBUF    26112
#define DYL     13056
#define OFF_XB  93696          /* L1 only: 2 x-buffers */
#define DB1 10752
#define DB2  9984

__host__ __device__ constexpr int smem_total_c(int CIN, int COUT, int MODE_IN) {
    return OFF_XB +
           (MODE_IN == 0 ? 2 * NC * ((MTILE / COUT) * CIN + 4) * 4 : 0);
}

// ---------------- PTX helpers ----------------------------------------------
__device__ __forceinline__ uint32_t smem_u32(const void* p) {
    uint32_t a;
    asm("{ .reg .u64 t; cvta.to.shared.u64 t, %1; cvt.u32.u64 %0, t; }"
        : "=r"(a) : "l"(p));
    return a;
}
__device__ __forceinline__ void ldsm_x4(uint32_t* r, uint32_t addr) {
    asm volatile("ldmatrix.sync.aligned.m8n8.x4.shared.b16 {%0,%1,%2,%3}, [%4];"
                 : "=r"(r[0]), "=r"(r[1]), "=r"(r[2]), "=r"(r[3]) : "r"(addr));
}
__device__ __forceinline__ void ldsm_x4t(uint32_t* r, uint32_t addr) {
    asm volatile("ldmatrix.sync.aligned.m8n8.x4.trans.shared.b16 {%0,%1,%2,%3}, [%4];"
                 : "=r"(r[0]), "=r"(r[1]), "=r"(r[2]), "=r"(r[3]) : "r"(addr));
}
__device__ __forceinline__ void mma_bf16(float* c, const uint32_t* a,
                                         uint32_t b0, uint32_t b1) {
    asm volatile(
        "mma.sync.aligned.m16n8k16.row.col.f32.bf16.bf16.f32 "
        "{%0,%1,%2,%3}, {%4,%5,%6,%7}, {%8,%9}, {%0,%1,%2,%3};"
        : "+f"(c[0]), "+f"(c[1]), "+f"(c[2]), "+f"(c[3])
        : "r"(a[0]), "r"(a[1]), "r"(a[2]), "r"(a[3]), "r"(b0), "r"(b1));
}
// packed fp32x2
__device__ __forceinline__ uint64_t pk64(float lo, float hi) {
    uint64_t r; asm("mov.b64 %0, {%1, %2};" : "=l"(r) : "f"(lo), "f"(hi));
    return r;
}
__device__ __forceinline__ uint64_t splat64(float v) {
    uint64_t r; asm("mov.b64 %0, {%1, %1};" : "=l"(r) : "f"(v));
    return r;
}
__device__ __forceinline__ void fma64(uint64_t& d, uint64_t a, uint64_t b) {
    asm("fma.rn.f32x2 %0, %1, %2, %0;" : "+l"(d) : "l"(a), "l"(b));
}
__device__ __forceinline__ uint64_t mul64(uint64_t a, uint64_t b) {
    uint64_t r; asm("mul.rn.f32x2 %0, %1, %2;" : "=l"(r) : "l"(a), "l"(b));
    return r;
}
__device__ __forceinline__ void unpk64(float& lo, float& hi, uint64_t v) {
    asm("mov.b64 {%0, %1}, %2;" : "=f"(lo), "=f"(hi) : "l"(v));
}
__device__ __forceinline__ uint32_t cvt_bf16x2(float v1, float v0) {
    uint32_t r; asm("cvt.rn.bf16x2.f32 %0, %1, %2;" : "=r"(r) : "f"(v1), "f"(v0));
    return r;
}
__device__ __forceinline__ void split2(float v0, float v1,
                                       uint32_t& hp, uint32_t& lp) {
    hp = cvt_bf16x2(v1, v0);
    const float f0 = __uint_as_float(hp << 16);
    const float f1 = __uint_as_float(hp & 0xFFFF0000u);
    lp = cvt_bf16x2(v1 - f1, v0 - f0);
}

// ---------------- problem constants -----------------------------------------
__host__ __device__ __forceinline__ constexpr int ggrp(int k) {
    return (k < 1) ? 0 : (k < 6) ? 1 : (k < 15) ? 2 : (k < 28) ? 3 : 4;
}
__device__ __forceinline__ float scl_of(int k) {
    const int g = ggrp(k);
    return g == 0 ? 1.77245385090552f
         : g == 1 ? 0.79266545952121f
         : g == 2 ? 0.59081795030184f
         : g == 3 ? 0.49159027f
         :          0.42988321f;
}

// ---------------- setup: split B matrices, expand W -------------------------
__device__ void expand_w(const float* __restrict__ w, float* __restrict__ dst,
                         int CIN, int COUT, int tid) {
    const int n = 5 * CIN * COUT;
    for (int i = tid; i < n; i += NTT) {
        int g = i / (CIN * COUT);
        int r = i - g * (CIN * COUT);
        int c = r / COUT, o = r - c * COUT;
        dst[i] = w[(o * CIN + c) * 5 + g];
    }
}

__global__ void build_B(const float* __restrict__ sft,
                        const float* __restrict__ isft,
                        const float* __restrict__ w1, const float* __restrict__ w2,
                        const float* __restrict__ w3, const float* __restrict__ w4,
                        const float* __restrict__ w5, const float* __restrict__ w6) {
    const int tid = threadIdx.x;
    for (int i = tid; i < 96 * 48; i += NTT) {     // B1[n=p(96)][k(48)]
        int n = i / 48, k = i - n * 48;
        float v = (n < ND && k < NC) ? isft[n * NC + k] : 0.f;
        __nv_bfloat16 hi = __float2bfloat16(v);
        g_B1h[i] = hi;
        g_B1l[i] = __float2bfloat16(v - __bfloat162float(hi));
    }
    for (int i = tid; i < 48 * 96; i += NTT) {     // B2[n=k(48)][k=p(96)]
        int n = i / 96, p = i - n * 96;
        float v = (n < NC && p < ND) ? sft[n * ND + p] : 0.f;
        __nv_bfloat16 hi = __float2bfloat16(v);
        g_B2h[i] = hi;
        g_B2l[i] = __float2bfloat16(v - __bfloat162float(hi));
    }
    expand_w(w1, g_Wexp + 0,     4,  16, tid);
    expand_w(w2, g_Wexp + 320,   16, 32, tid);
    expand_w(w3, g_Wexp + 2880,  32, 64, tid);
    expand_w(w4, g_Wexp + 13120, 64, 32, tid);
    expand_w(w5, g_Wexp + 23360, 32, 16, tid);
    expand_w(w6, g_Wexp + 25920, 16, 4,  tid);
}

// sconv over k in [K0,K0+KN), groups [G0,G0+GN): one thread, FOUR rows
// m0..m0+3, fp32x2 row-pair accumulators. W via float4 gmem.
template <int K0, int KN, int G0, int GN, int CIN, int COUT, int XSTR, int MODE_IN>
__device__ __forceinline__ void sconv_seg4(const float* __restrict__ xb,
                                           const float* __restrict__ wp,
                                           __nv_bfloat16* __restrict__ yh,
                                           __nv_bfloat16* __restrict__ yl,
                                           int m0) {
    constexpr size_t KS = (size_t)NB_TOTAL * CIN;
    uint64_t acc2[2][KN];
#pragma unroll
    for (int jp = 0; jp < 2; jp++)
#pragma unroll
        for (int kk = 0; kk < KN; kk++) acc2[jp][kk] = 0ull;

#pragma unroll 1
    for (int cb = 0; cb < CIN; cb += 4) {
        uint64_t w2[4][GN][2];
#pragma unroll
        for (int cc = 0; cc < 4; cc++)
#pragma unroll
            for (int gi = 0; gi < GN; gi++) {
                const float4 t = __ldg(reinterpret_cast<const float4*>(
                    wp + (size_t)((G0 + gi) * CIN + cb + cc) * COUT));
                w2[cc][gi][0] = pk64(t.x, t.y);
                w2[cc][gi][1] = pk64(t.z, t.w);
            }
#pragma unroll
        for (int kk = 0; kk < KN; kk++) {
            float4 xv;
            if constexpr (MODE_IN == 0)
                xv = *reinterpret_cast<const float4*>(xb + (K0 + kk) * XSTR + cb);
            else
                xv = __ldg(reinterpret_cast<const float4*>(
                        xb + (size_t)(K0 + kk) * KS + cb));
            const int gi = ggrp(K0 + kk) - G0;
            const uint64_t x0 = splat64(xv.x), x1 = splat64(xv.y);
            const uint64_t x2 = splat64(xv.z), x3 = splat64(xv.w);
#pragma unroll
            for (int jp = 0; jp < 2; jp++) {
                fma64(acc2[jp][kk], x0, w2[0][gi][jp]);
                fma64(acc2[jp][kk], x1, w2[1][gi][jp]);
                fma64(acc2[jp][kk], x2, w2[2][gi][jp]);
                fma64(acc2[jp][kk], x3, w2[3][gi][jp]);
            }
        }
    }
#pragma unroll
    for (int kk = 0; kk < KN; kk++) {
        const uint64_t s2 = splat64(scl_of(K0 + kk));
        const uint64_t v01 = mul64(acc2[0][kk], s2);
        const uint64_t v23 = mul64(acc2[1][kk], s2);
        float a, b, c, d;
        unpk64(a, b, v01);
        unpk64(c, d, v23);
        uint2 ph, pl;
        split2(a, b, ph.x, pl.x);
        split2(c, d, ph.y, pl.y);
        *reinterpret_cast<uint2*>(yh + (K0 + kk) * MSTR + m0) = ph;
        *reinterpret_cast<uint2*>(yl + (K0 + kk) * MSTR + m0) = pl;
    }
}

// sconv dispatch over 8 warp k-segments
template <int CIN, int COUT, int XSTR, int MODE_IN>
__device__ __forceinline__ void sconv_run(int q, const float* xb,
                                          const float* wp,
                                          __nv_bfloat16* yh, __nv_bfloat16* yl,
                                          int m0) {
    if      (q == 0) sconv_seg4< 0, 6, 0, 2, CIN, COUT, XSTR, MODE_IN>(xb, wp, yh, yl, m0);
    else if (q == 1) sconv_seg4< 6, 6, 2, 1, CIN, COUT, XSTR, MODE_IN>(xb, wp, yh, yl, m0);
    else if (q == 2) sconv_seg4<12, 6, 2, 2, CIN, COUT, XSTR, MODE_IN>(xb, wp, yh, yl, m0);
    else if (q == 3) sconv_seg4<18, 5, 3, 1, CIN, COUT, XSTR, MODE_IN>(xb, wp, yh, yl, m0);
    else if (q == 4) sconv_seg4<23, 5, 3, 1, CIN, COUT, XSTR, MODE_IN>(xb, wp, yh, yl, m0);
    else if (q == 5) sconv_seg4<28, 6, 4, 1, CIN, COUT, XSTR, MODE_IN>(xb, wp, yh, yl, m0);
    else if (q == 6) sconv_seg4<34, 6, 4, 1, CIN, COUT, XSTR, MODE_IN>(xb, wp, yh, yl, m0);
    else             sconv_seg4<40, 5, 4, 1, CIN, COUT, XSTR, MODE_IN>(xb, wp, yh, yl, m0);
}

// ---------------- per-layer persistent kernel -------------------------------
template <int CIN, int COUT, int MODE_IN, int MODE_OUT>
__global__ void __launch_bounds__(NTT, 2)
scnn_layer(const float* __restrict__ in, const float* __restrict__ wexp,
           float* __restrict__ out, int ntiles) {
    constexpr int TB   = MTILE / COUT;
    constexpr int MIN_ = TB * CIN;
    constexpr int XSTR = MIN_ + 4;
    constexpr int XBF  = NC * XSTR;        // floats per x buffer
    constexpr int QTR  = COUT / 4;
    static_assert(MTILE % COUT == 0 && CIN % 4 == 0 && COUT % 4 == 0, "cfg");

    extern __shared__ char smc[];
    const uint32_t sb = smem_u32(smc);
    const int tid = threadIdx.x, wid = tid >> 5, lane = tid & 31;
    const int stride = gridDim.x;

    // ---- one-time setup: zero Y buffers (covers pads), copy B tiles --------
    for (int i = tid; i < (OFF_XB - OFF_Y) / 4; i += NTT)
        ((uint32_t*)(smc + OFF_Y))[i] = 0;
    {
        const uint32_t* s1h = (const uint32_t*)g_B1h;
        const uint32_t* s1l = (const uint32_t*)g_B1l;
        uint32_t* d1h = (uint32_t*)(smc + OFF_B1H);
        uint32_t* d1l = (uint32_t*)(smc + OFF_B1L);
        for (int i = tid; i < 96 * 24; i += NTT) {
            int n = i / 24, kk = i - n * 24;
            d1h[(n * B1STR) / 2 + kk] = s1h[i];
            d1l[(n * B1STR) / 2 + kk] = s1l[i];
        }
        const uint32_t* s2h = (const uint32_t*)g_B2h;
        const uint32_t* s2l = (const uint32_t*)g_B2l;
        uint32_t* d2h = (uint32_t*)(smc + OFF_B2H);
        uint32_t* d2l = (uint32_t*)(smc + OFF_B2L);
        for (int i = tid; i < 48 * 48; i += NTT) {
            int n = i / 48, kk = i - n * 48;
            d2h[(n * B2STR) / 2 + kk] = s2h[i];
            d2l[(n * B2STR) / 2 + kk] = s2l[i];
        }
    }

    // ---- loop-invariant addressing (8 warps, m16 each) ---------------------
    const int mb = wid * 16;
    const int g = lane >> 3, rr = lane & 7;
    const int qr = lane >> 2, qc = lane & 3;

    const uint32_t aOff =                       // offset within a Y buffer
        (((g >> 1) * 8 + rr) * MSTR + mb + (g & 1) * 8) * 2;
    const uint32_t bB1 = sb + OFF_B1H +
        (((g >> 1) * 8 + rr) * B1STR + (g & 1) * 8) * 2;
    const uint32_t bB2 = sb + OFF_B2H +
        (((g >> 1) * 8 + rr) * B2STR + (g & 1) * 8) * 2;

    // sconv mapping: warp = k-segment, lane = row-quad
    const int q   = wid;
    const int tS  = lane / QTR;
    const int oS  = lane - tS * QTR;
    const int m0S = tS * COUT + 4 * oS;
    const float* wp = wexp + 4 * oS;

    // x staging helper (L1 only)
    auto stage_x = [&](int tt, int buf) {
        const size_t bi = (size_t)tt * (MIN_ * NC);
        float* dst = (float*)(smc + OFF_XB) + buf * XBF;
        for (int i = tid; i < MIN_ * NC; i += NTT) {
            int m = i / NC, k = i - m * NC;
            dst[k * XSTR + m] = in[bi + i];
        }
    };

    // sconv wrapper for tile tt into buffer pn
    auto do_sconv = [&](int tt, int pn) {
        const float* xb;
        if constexpr (MODE_IN == 0) {
            xb = (const float*)(smc + OFF_XB) + pn * XBF + tS * CIN;
        } else {
            int b = tt * TB + tS;
            if (b >= NB_TOTAL) b = NB_TOTAL - 1;   // clamp; stores guarded
            xb = in + (size_t)b * CIN;
        }
        __nv_bfloat16* yh = (__nv_bfloat16*)(smc + OFF_Y + pn * YBUF);
        __nv_bfloat16* yl = (__nv_bfloat16*)(smc + OFF_Y + pn * YBUF + DYL);
        sconv_run<CIN, COUT, XSTR, MODE_IN>(q, xb, wp, yh, yl, m0S);
    };

    // ---- prologue -----------------------------------------------------------
    int t = blockIdx.x;
    if constexpr (MODE_IN == 0) {
        stage_x(t, 0);
        __syncthreads();
        do_sconv(t, 0);
        if (t + stride < ntiles) stage_x(t + stride, 1);
    } else {
        do_sconv(t, 0);
    }
    __syncthreads();

    // ---- persistent tile loop: GEMM(t) | sconv(t+stride), ONE barrier ------
    int p = 0;
    for (; t < ntiles; t += stride) {
        const uint32_t yb = sb + OFF_Y + p * YBUF;

        // GEMM(t): pc-fused GEMM1 -> repack -> GEMM2
        uint32_t ah[3][4];
#pragma unroll
        for (int ks = 0; ks < 3; ks++)
            ldsm_x4t(ah[ks], yb + aOff + ks * (16 * MSTR * 2));

        float c2[6][4];
#pragma unroll
        for (int i = 0; i < 6; i++)
#pragma unroll
            for (int j = 0; j < 4; j++) c2[i][j] = 0.f;

#pragma unroll
        for (int pc = 0; pc < 6; pc++) {
            float c1t[2][4];
#pragma unroll
            for (int i = 0; i < 2; i++)
#pragma unroll
                for (int j = 0; j < 4; j++) c1t[i][j] = 0.f;

#pragma unroll
            for (int ks = 0; ks < 3; ks++) {
                uint32_t al[4];
                ldsm_x4t(al, yb + aOff + ks * (16 * MSTR * 2) + DYL);
                const uint32_t bo = bB1 + ks * 32 + pc * (16 * B1STR * 2);
                uint32_t bh[4], bl[4];
                ldsm_x4(bh, bo);
                ldsm_x4(bl, bo + DB1);
                mma_bf16(c1t[0], ah[ks], bh[0], bh[1]);
                mma_bf16(c1t[0], ah[ks], bl[0], bl[1]);
                mma_bf16(c1t[0], al, bh[0], bh[1]);
                mma_bf16(c1t[1], ah[ks], bh[2], bh[3]);
                mma_bf16(c1t[1], ah[ks], bl[2], bl[3]);
                mma_bf16(c1t[1], al, bh[2], bh[3]);
            }
            uint32_t a2h[4], a2l[4];
#pragma unroll
            for (int u = 0; u < 2; u++)
#pragma unroll
                for (int v = 0; v < 2; v++) {
                    const float p0 = fmaxf(c1t[u][2 * v], 0.f);
                    const float p1 = fmaxf(c1t[u][2 * v + 1], 0.f);
                    split2(p0, p1, a2h[2 * u + v], a2l[2 * u + v]);
                }
#pragma unroll
            for (int np = 0; np < 3; np++) {
                const uint32_t bo = bB2 + pc * 32 + np * (16 * B2STR * 2);
                uint32_t bh[4], bl[4];
                ldsm_x4(bh, bo);
                ldsm_x4(bl, bo + DB2);
                mma_bf16(c2[2 * np], a2h, bh[0], bh[1]);
                mma_bf16(c2[2 * np], a2h, bl[0], bl[1]);
                mma_bf16(c2[2 * np], a2l, bh[0], bh[1]);
                mma_bf16(c2[2 * np + 1], a2h, bh[2], bh[3]);
                mma_bf16(c2[2 * np + 1], a2h, bl[2], bl[3]);
                mma_bf16(c2[2 * np + 1], a2l, bh[2], bh[3]);
            }
        }

        // store c2 straight to gmem (guarded)
#pragma unroll
        for (int j = 0; j < 6; j++) {
            const int col = 8 * j + 2 * qc;
#pragma unroll
            for (int h = 0; h < 2; h++) {
                const int row = mb + qr + 8 * h;
                const float v0 = c2[j][2 * h];
                const float v1 = c2[j][2 * h + 1];
                if constexpr (MODE_OUT == 1) {       // [k][b][ch]
                    const int b = t * TB + row / COUT;
                    const int ch = row % COUT;
                    if (b < NB_TOTAL) {
                        if (col < NC)
                            out[((size_t)col * NB_TOTAL + b) * COUT + ch] = v0;
                        if (col + 1 < NC)
                            out[((size_t)(col + 1) * NB_TOTAL + b) * COUT + ch] = v1;
                    }
                } else {                             // [b][ch][k] (L6)
                    if (t * TB + row / COUT < NB_TOTAL) {
                        const size_t ro = ((size_t)t * MTILE + row) * NC;
                        if (col < NC)     out[ro + col]     = v0;
                        if (col + 1 < NC) out[ro + col + 1] = v1;
                    }
                }
            }
        }

        // sconv(t+stride) into the other Y buffer (overlaps GEMM across warps)
        const int tn = t + stride;
        if (tn < ntiles) do_sconv(tn, p ^ 1);
        if constexpr (MODE_IN == 0) {
            if (tn + stride < ntiles) stage_x(tn + stride, p);
        }
        __syncthreads();
        p ^= 1;
    }
}

// ---------------- host ------------------------------------------------------
extern "C" void kernel_launch(void* const* d_in, const int* in_sizes, int n_in,
                              void* d_out, int out_size) {
    (void)in_sizes; (void)n_in; (void)out_size;

    const float* x    = (const float*)d_in[0];
    const float* sft  = (const float*)d_in[1];
    const float* isft = (const float*)d_in[2];
    const float* w1   = (const float*)d_in[3];
    const float* w2   = (const float*)d_in[4];
    const float* w3   = (const float*)d_in[5];
    const float* w4   = (const float*)d_in[6];
    const float* w5   = (const float*)d_in[7];
    const float* w6   = (const float*)d_in[8];
    float* out = (float*)d_out;

    float *bufA = nullptr, *bufB = nullptr, *wexp = nullptr;
    cudaGetSymbolAddress((void**)&bufA, g_bufA);
    cudaGetSymbolAddress((void**)&bufB, g_bufB);
    cudaGetSymbolAddress((void**)&wexp, g_Wexp);

    cudaFuncSetAttribute((const void*)scnn_layer<4, 16, 0, 1>,
        cudaFuncAttributeMaxDynamicSharedMemorySize, smem_total_c(4, 16, 0));
    cudaFuncSetAttribute((const void*)scnn_layer<16, 32, 1, 1>,
        cudaFuncAttributeMaxDynamicSharedMemorySize, smem_total_c(16, 32, 1));
    cudaFuncSetAttribute((const void*)scnn_layer<32, 64, 1, 1>,
        cudaFuncAttributeMaxDynamicSharedMemorySize, smem_total_c(32, 64, 1));
    cudaFuncSetAttribute((const void*)scnn_layer<64, 32, 1, 1>,
        cudaFuncAttributeMaxDynamicSharedMemorySize, smem_total_c(64, 32, 1));
    cudaFuncSetAttribute((const void*)scnn_layer<32, 16, 1, 1>,
        cudaFuncAttributeMaxDynamicSharedMemorySize, smem_total_c(32, 16, 1));
    cudaFuncSetAttribute((const void*)scnn_layer<16, 4, 1, 0>,
        cudaFuncAttributeMaxDynamicSharedMemorySize, smem_total_c(16, 4, 1));

    build_B<<<1, NTT>>>(sft, isft, w1, w2, w3, w4, w5, w6);

    const int GRID2 = 296;   // 2 CTAs/SM
    // TB = 128/COUT -> tiles: L1 6250, L2 12500, L3 25000, L4 12500, L5 6250,
    // L6 ceil(50000/32) = 1563 (guarded tail)
    scnn_layer<4, 16, 0, 1><<<GRID2, NTT, smem_total_c(4, 16, 0)>>>(
        x, wexp + 0, bufA, NB_TOTAL / 8);
    scnn_layer<16, 32, 1, 1><<<GRID2, NTT, smem_total_c(16, 32, 1)>>>(
        bufA, wexp + 320, bufB, NB_TOTAL / 4);
    scnn_layer<32, 64, 1, 1><<<GRID2, NTT, smem_total_c(32, 64, 1)>>>(
        bufB, wexp + 2880, bufA, NB_TOTAL / 2);
    scnn_layer<64, 32, 1, 1><<<GRID2, NTT, smem_total_c(64, 32, 1)>>>(
        bufA, wexp + 13120, bufB, NB_TOTAL / 4);
    scnn_layer<32, 16, 1, 1><<<GRID2, NTT, smem_total_c(32, 16, 1)>>>(
        bufB, wexp + 23360, bufA, NB_TOTAL / 8);
    scnn_layer<16, 4, 1, 0><<<GRID2, NTT, smem_total_c(16, 4, 1)>>>(
        bufA, wexp + 25920, out, (NB_TOTAL + 31) / 32);
}